// round 5
// baseline (speedup 1.0000x reference)
#include <cuda_runtime.h>
#include <math.h>
#include <stdint.h>

#define BATCH 32
#define HDIM 56
#define WDIM 56
#define CDIM 256
#define NHEAD 8
#define HEADD 32
#define WS 7
#define NT 49
#define SHIFT 3
#define NWIN 64
#define BW (BATCH*NWIN)
#define TOK (BW*NT)
#define QKV_N 768
#define SPAD 36
#define SSTR 60

// Static device scratch (allocation-free rule).
__device__ float g_q[BW*NHEAD*NT*HEADD];
__device__ float g_k[BW*NHEAD*NT*HEADD];
__device__ float g_v[BW*NHEAD*NT*HEADD];
__device__ float g_ao[TOK*CDIM];
__device__ float g_bias[4*NHEAD*NT*NT];   // fused (bias + shift-mask) per class/head

__device__ __forceinline__ uint32_t f2tf(float f) {
    uint32_t u;
    asm("cvt.rna.tf32.f32 %0, %1;" : "=r"(u) : "f"(f));
    return u;
}
__device__ __forceinline__ float f2tff(float f) {
    return __uint_as_float(f2tf(f));
}

__device__ __forceinline__ void mma_tf32(float c[4],
                                         uint32_t a0, uint32_t a1, uint32_t a2, uint32_t a3,
                                         uint32_t b0, uint32_t b1) {
    asm volatile(
        "mma.sync.aligned.m16n8k8.row.col.f32.tf32.tf32.f32 "
        "{%0,%1,%2,%3}, {%4,%5,%6,%7}, {%8,%9}, {%0,%1,%2,%3};\n"
        : "+f"(c[0]), "+f"(c[1]), "+f"(c[2]), "+f"(c[3])
        : "r"(a0), "r"(a1), "r"(a2), "r"(a3), "r"(b0), "r"(b1));
}

// ---------------------------------------------------------------------------
// Fused bias + shift-mask precompute. cls bit1 = (wh==7), bit0 = (ww==7).
// ---------------------------------------------------------------------------
__global__ void bias_pre2(const float* __restrict__ relt, const int* __restrict__ reli) {
    int idx = blockIdx.x * 256 + threadIdx.x;
    if (idx >= 4*NHEAD*NT*NT) return;
    int cls = idx / (NHEAD*NT*NT);
    int rem = idx - cls*(NHEAD*NT*NT);
    int nh  = rem / (NT*NT);
    int ij  = rem - nh*(NT*NT);
    int i = ij / NT, j = ij - (ij/NT)*NT;
    float b = relt[reli[ij]*NHEAD + nh];
    int ri = i / WS, ci = i - (i/WS)*WS;
    int rj = j / WS, cj = j - (j/WS)*WS;
    int ghi = (cls & 2) ? ((ri < 4) ? 1 : 2) : 0;
    int gwi = (cls & 1) ? ((ci < 4) ? 1 : 2) : 0;
    int ghj = (cls & 2) ? ((rj < 4) ? 1 : 2) : 0;
    int gwj = (cls & 1) ? ((cj < 4) ? 1 : 2) : 0;
    float mk = (ghi == ghj && gwi == gwj) ? 0.f : -100.f;
    g_bias[idx] = b + mk;
}

// ---------------------------------------------------------------------------
// QKV GEMM (tf32 tensor cores)
// ---------------------------------------------------------------------------
__global__ __launch_bounds__(256) void qkv_tc(
    const float* __restrict__ x,
    const float* __restrict__ w,
    const float* __restrict__ bias)
{
    __shared__ __align__(16) float As[128*SPAD];
    __shared__ __align__(16) float Bs[128*SPAD];
    __shared__ int rowoff[128];

    const int tid = threadIdx.x;
    const int m0 = blockIdx.x * 128;
    const int n0 = blockIdx.y * 128;

    if (tid < 128) {
        int m  = m0 + tid;
        int bw = m / NT; int t = m - bw*NT;
        int b  = bw >> 6; int wi = bw & 63;
        int wh = wi >> 3; int wwn = wi & 7;
        int r  = t / WS;  int c = t - r*WS;
        int hs = wh*WS + r + SHIFT; if (hs >= HDIM) hs -= HDIM;
        int ws = wwn*WS + c + SHIFT; if (ws >= WDIM) ws -= WDIM;
        rowoff[tid] = ((b*HDIM + hs)*WDIM + ws) * CDIM;
    }
    __syncthreads();

    const int warp = tid >> 5, lane = tid & 31;
    const int wm = warp >> 2, wn = warp & 3;
    const int g = lane >> 2, q = lane & 3;

    float acc[4][4][4];
    #pragma unroll
    for (int mi = 0; mi < 4; mi++)
        #pragma unroll
        for (int ni = 0; ni < 4; ni++)
            #pragma unroll
            for (int e = 0; e < 4; e++) acc[mi][ni][e] = 0.f;

    int lr[4], lk[4];
    #pragma unroll
    for (int i = 0; i < 4; i++) {
        int lin = tid + i*256;
        lr[i] = lin >> 3;
        lk[i] = (lin & 7) * 4;
    }

    float4 abuf[4], bbuf[4];
    #pragma unroll
    for (int i = 0; i < 4; i++) {
        abuf[i] = *(const float4*)(x + rowoff[lr[i]] + lk[i]);
        bbuf[i] = *(const float4*)(w + (size_t)(n0 + lr[i])*CDIM + lk[i]);
    }

    for (int kt = 0; kt < 8; kt++) {
        #pragma unroll
        for (int i = 0; i < 4; i++) {
            float* ap = &As[lr[i]*SPAD + lk[i]];
            ap[0] = f2tff(abuf[i].x); ap[1] = f2tff(abuf[i].y);
            ap[2] = f2tff(abuf[i].z); ap[3] = f2tff(abuf[i].w);
            float* bp = &Bs[lr[i]*SPAD + lk[i]];
            bp[0] = f2tff(bbuf[i].x); bp[1] = f2tff(bbuf[i].y);
            bp[2] = f2tff(bbuf[i].z); bp[3] = f2tff(bbuf[i].w);
        }
        __syncthreads();

        if (kt < 7) {
            int k0 = (kt+1)*32;
            #pragma unroll
            for (int i = 0; i < 4; i++) {
                abuf[i] = *(const float4*)(x + rowoff[lr[i]] + k0 + lk[i]);
                bbuf[i] = *(const float4*)(w + (size_t)(n0 + lr[i])*CDIM + k0 + lk[i]);
            }
        }

        #pragma unroll
        for (int ks = 0; ks < 4; ks++) {
            const int kc = ks*8;
            uint32_t a[4][4];
            #pragma unroll
            for (int mi = 0; mi < 4; mi++) {
                int r = wm*64 + mi*16;
                a[mi][0] = __float_as_uint(As[(r+g  )*SPAD + kc + q    ]);
                a[mi][1] = __float_as_uint(As[(r+g+8)*SPAD + kc + q    ]);
                a[mi][2] = __float_as_uint(As[(r+g  )*SPAD + kc + q + 4]);
                a[mi][3] = __float_as_uint(As[(r+g+8)*SPAD + kc + q + 4]);
            }
            uint32_t b[4][2];
            #pragma unroll
            for (int ni = 0; ni < 4; ni++) {
                int cb = wn*32 + ni*8;
                b[ni][0] = __float_as_uint(Bs[(cb+g)*SPAD + kc + q    ]);
                b[ni][1] = __float_as_uint(Bs[(cb+g)*SPAD + kc + q + 4]);
            }
            #pragma unroll
            for (int mi = 0; mi < 4; mi++)
                #pragma unroll
                for (int ni = 0; ni < 4; ni++)
                    mma_tf32(acc[mi][ni], a[mi][0], a[mi][1], a[mi][2], a[mi][3],
                             b[ni][0], b[ni][1]);
        }
        __syncthreads();
    }

    const float scale = 0.17677669529663687f;
    #pragma unroll
    for (int mi = 0; mi < 4; mi++) {
        #pragma unroll
        for (int half = 0; half < 2; half++) {
            int mrow = wm*64 + mi*16 + g + half*8;
            int m  = m0 + mrow;
            int bw = m / NT; int t = m - bw*NT;
            int base = bw*12544 + t*32;
            #pragma unroll
            for (int ni = 0; ni < 4; ni++) {
                int col = n0 + wn*32 + ni*8 + q*2;
                float v0 = acc[mi][ni][half*2+0] + bias[col];
                float v1 = acc[mi][ni][half*2+1] + bias[col+1];
                int which = col >> 8;
                int rem   = col & 255;
                int nh = rem >> 5; int d = rem & 31;
                int dst = base + nh*1568 + d;
                if (which == 0)      { g_q[dst] = v0*scale; g_q[dst+1] = v1*scale; }
                else if (which == 1) { g_k[dst] = v0;       g_k[dst+1] = v1; }
                else                 { g_v[dst] = v0;       g_v[dst+1] = v1; }
            }
        }
    }
}

// ---------------------------------------------------------------------------
// Attention v3: 128 threads/block, one (window, head) per block.
// Warp w owns S-rows [16w, 16w+16): S = QK^T via mma (A cached in regs),
// softmax fully in registers (quad shuffles), P -> smem (aliased over Q),
// O = P V via mma.
// ---------------------------------------------------------------------------
__global__ __launch_bounds__(128) void attn_tc3()
{
    __shared__ __align__(16) float sbuf[NT*SSTR];   // P (49x60); prologue holds Q (49x36)
    __shared__ __align__(16) float sk[NT*SPAD];
    __shared__ __align__(16) float svt[HEADD*SSTR]; // V^T, cols 49..55 zeroed

    const int bw = blockIdx.x;
    const int nh = blockIdx.y;
    const int tid = threadIdx.x;

    const float* qb = g_q + bw*12544 + nh*1568;
    const float* kb = g_k + bw*12544 + nh*1568;
    const float* vb = g_v + bw*12544 + nh*1568;

    for (int i = tid; i < 392; i += 128) {
        int e = i*4; int t = e >> 5; int d = e & 31;
        float4 q4 = *(const float4*)(qb + e);
        float4 k4 = *(const float4*)(kb + e);
        float4 v4 = *(const float4*)(vb + e);
        float* qp = &sbuf[t*SPAD + d];
        qp[0]=f2tff(q4.x); qp[1]=f2tff(q4.y); qp[2]=f2tff(q4.z); qp[3]=f2tff(q4.w);
        float* kp = &sk[t*SPAD + d];
        kp[0]=f2tff(k4.x); kp[1]=f2tff(k4.y); kp[2]=f2tff(k4.z); kp[3]=f2tff(k4.w);
        svt[(d+0)*SSTR + t] = f2tff(v4.x);
        svt[(d+1)*SSTR + t] = f2tff(v4.y);
        svt[(d+2)*SSTR + t] = f2tff(v4.z);
        svt[(d+3)*SSTR + t] = f2tff(v4.w);
    }
    for (int i = tid; i < 224; i += 128)
        svt[(i/7)*SSTR + 49 + (i - (i/7)*7)] = 0.f;
    __syncthreads();

    const int warp = tid >> 5, lane = tid & 31;
    const int g = lane >> 2, q = lane & 3;

    const int wi  = bw & 63;
    const int cls = ((((wi >> 3) == 7) ? 2 : 0) | (((wi & 7) == 7) ? 1 : 0));
    const float* bb = g_bias + (cls*NHEAD + nh)*(NT*NT);

    const int i0 = warp*16;
    const int r0 = i0 + g, r1 = r0 + 8;
    const int ra = min(r0, 48), rb = min(r1, 48);
    const bool v0ok = (r0 < 49), v1ok = (r1 < 49);

    // ---- S = Q K^T (A fragments cached across all 7 n-tiles) ----
    uint32_t a[4][4];
    #pragma unroll
    for (int k4i = 0; k4i < 4; k4i++) {
        int kc = k4i*8;
        a[k4i][0] = __float_as_uint(sbuf[ra*SPAD + kc + q    ]);
        a[k4i][1] = __float_as_uint(sbuf[rb*SPAD + kc + q    ]);
        a[k4i][2] = __float_as_uint(sbuf[ra*SPAD + kc + q + 4]);
        a[k4i][3] = __float_as_uint(sbuf[rb*SPAD + kc + q + 4]);
    }
    float c[7][4];
    #pragma unroll
    for (int nt = 0; nt < 7; nt++) { c[nt][0]=0.f; c[nt][1]=0.f; c[nt][2]=0.f; c[nt][3]=0.f; }
    #pragma unroll
    for (int nt = 0; nt < 7; nt++) {
        int rn = min(nt*8 + g, 48);
        #pragma unroll
        for (int k4i = 0; k4i < 4; k4i++) {
            int kc = k4i*8;
            uint32_t b0 = __float_as_uint(sk[rn*SPAD + kc + q    ]);
            uint32_t b1 = __float_as_uint(sk[rn*SPAD + kc + q + 4]);
            mma_tf32(c[nt], a[k4i][0], a[k4i][1], a[k4i][2], a[k4i][3], b0, b1);
        }
    }

    // ---- bias(+mask) add, in-register ----
    float mx0 = -1e30f, mx1 = -1e30f;
    #pragma unroll
    for (int nt = 0; nt < 7; nt++) {
        #pragma unroll
        for (int bc = 0; bc < 2; bc++) {
            int col = nt*8 + 2*q + bc;
            bool cok = (col < 49);
            float t0 = (v0ok && cok) ? (c[nt][bc]   + __ldg(&bb[r0*NT + col])) : -1e30f;
            float t1 = (v1ok && cok) ? (c[nt][2+bc] + __ldg(&bb[r1*NT + col])) : -1e30f;
            c[nt][bc]   = t0;
            c[nt][2+bc] = t1;
            mx0 = fmaxf(mx0, t0);
            mx1 = fmaxf(mx1, t1);
        }
    }
    __syncthreads();   // all reads of sbuf(Q)/sk done; sbuf can be reused as P

    // ---- softmax in registers (rows live in lane quads) ----
    mx0 = fmaxf(mx0, __shfl_xor_sync(0xffffffffu, mx0, 1));
    mx0 = fmaxf(mx0, __shfl_xor_sync(0xffffffffu, mx0, 2));
    mx1 = fmaxf(mx1, __shfl_xor_sync(0xffffffffu, mx1, 1));
    mx1 = fmaxf(mx1, __shfl_xor_sync(0xffffffffu, mx1, 2));
    float s0 = 0.f, s1 = 0.f;
    #pragma unroll
    for (int nt = 0; nt < 7; nt++) {
        c[nt][0] = __expf(c[nt][0] - mx0); s0 += c[nt][0];
        c[nt][1] = __expf(c[nt][1] - mx0); s0 += c[nt][1];
        c[nt][2] = __expf(c[nt][2] - mx1); s1 += c[nt][2];
        c[nt][3] = __expf(c[nt][3] - mx1); s1 += c[nt][3];
    }
    s0 += __shfl_xor_sync(0xffffffffu, s0, 1);
    s0 += __shfl_xor_sync(0xffffffffu, s0, 2);
    s1 += __shfl_xor_sync(0xffffffffu, s1, 1);
    s1 += __shfl_xor_sync(0xffffffffu, s1, 2);
    float inv0 = 1.f / s0, inv1 = 1.f / s1;
    #pragma unroll
    for (int nt = 0; nt < 7; nt++) {
        #pragma unroll
        for (int bc = 0; bc < 2; bc++) {
            int col = nt*8 + 2*q + bc;
            if (v0ok) sbuf[r0*SSTR + col] = (col < 49) ? f2tff(c[nt][bc]  *inv0) : 0.f;
            if (v1ok) sbuf[r1*SSTR + col] = (col < 49) ? f2tff(c[nt][2+bc]*inv1) : 0.f;
        }
    }
    __syncthreads();

    // ---- O = P V (warp keeps its rows; P fragments hoisted across d-tiles) ----
    uint32_t pa[7][4];
    #pragma unroll
    for (int k7 = 0; k7 < 7; k7++) {
        int kc = k7*8;
        pa[k7][0] = __float_as_uint(sbuf[ra*SSTR + kc + q    ]);
        pa[k7][1] = __float_as_uint(sbuf[rb*SSTR + kc + q    ]);
        pa[k7][2] = __float_as_uint(sbuf[ra*SSTR + kc + q + 4]);
        pa[k7][3] = __float_as_uint(sbuf[rb*SSTR + kc + q + 4]);
    }
    #pragma unroll
    for (int nt = 0; nt < 4; nt++) {
        int n0 = nt*8;
        float cc[4] = {0.f, 0.f, 0.f, 0.f};
        #pragma unroll
        for (int k7 = 0; k7 < 7; k7++) {
            int kc = k7*8;
            uint32_t b0 = __float_as_uint(svt[(n0+g)*SSTR + kc + q    ]);
            uint32_t b1 = __float_as_uint(svt[(n0+g)*SSTR + kc + q + 4]);
            mma_tf32(cc, pa[k7][0], pa[k7][1], pa[k7][2], pa[k7][3], b0, b1);
        }
        int col = nh*32 + n0 + 2*q;
        if (v0ok)
            *(float2*)(g_ao + (size_t)(bw*NT + r0)*CDIM + col) = make_float2(cc[0], cc[1]);
        if (v1ok)
            *(float2*)(g_ao + (size_t)(bw*NT + r1)*CDIM + col) = make_float2(cc[2], cc[3]);
    }
}

// ---------------------------------------------------------------------------
// Proj GEMM (tf32 tensor cores) with fused window-reverse + un-shift scatter.
// ---------------------------------------------------------------------------
__global__ __launch_bounds__(256) void proj_tc(
    const float* __restrict__ w,
    const float* __restrict__ bias,
    float* __restrict__ out)
{
    __shared__ __align__(16) float As[128*SPAD];
    __shared__ __align__(16) float Bs[128*SPAD];
    __shared__ int rowdst[128];

    const int tid = threadIdx.x;
    const int m0 = blockIdx.x * 128;
    const int n0 = blockIdx.y * 128;

    if (tid < 128) {
        int m  = m0 + tid;
        int bw = m / NT; int t = m - bw*NT;
        int b  = bw >> 6; int wi = bw & 63;
        int wh = wi >> 3; int wwn = wi & 7;
        int r  = t / WS;  int c = t - r*WS;
        int hd = wh*WS + r + SHIFT; if (hd >= HDIM) hd -= HDIM;
        int wd = wwn*WS + c + SHIFT; if (wd >= WDIM) wd -= WDIM;
        rowdst[tid] = ((b*HDIM + hd)*WDIM + wd) * CDIM;
    }
    __syncthreads();

    const int warp = tid >> 5, lane = tid & 31;
    const int wm = warp >> 2, wn = warp & 3;
    const int g = lane >> 2, q = lane & 3;

    float acc[4][4][4];
    #pragma unroll
    for (int mi = 0; mi < 4; mi++)
        #pragma unroll
        for (int ni = 0; ni < 4; ni++)
            #pragma unroll
            for (int e = 0; e < 4; e++) acc[mi][ni][e] = 0.f;

    int lr[4], lk[4];
    #pragma unroll
    for (int i = 0; i < 4; i++) {
        int lin = tid + i*256;
        lr[i] = lin >> 3;
        lk[i] = (lin & 7) * 4;
    }

    float4 abuf[4], bbuf[4];
    #pragma unroll
    for (int i = 0; i < 4; i++) {
        abuf[i] = *(const float4*)(g_ao + (size_t)(m0 + lr[i])*CDIM + lk[i]);
        bbuf[i] = *(const float4*)(w + (size_t)(n0 + lr[i])*CDIM + lk[i]);
    }

    for (int kt = 0; kt < 8; kt++) {
        #pragma unroll
        for (int i = 0; i < 4; i++) {
            float* ap = &As[lr[i]*SPAD + lk[i]];
            ap[0] = f2tff(abuf[i].x); ap[1] = f2tff(abuf[i].y);
            ap[2] = f2tff(abuf[i].z); ap[3] = f2tff(abuf[i].w);
            float* bp = &Bs[lr[i]*SPAD + lk[i]];
            bp[0] = f2tff(bbuf[i].x); bp[1] = f2tff(bbuf[i].y);
            bp[2] = f2tff(bbuf[i].z); bp[3] = f2tff(bbuf[i].w);
        }
        __syncthreads();

        if (kt < 7) {
            int k0 = (kt+1)*32;
            #pragma unroll
            for (int i = 0; i < 4; i++) {
                abuf[i] = *(const float4*)(g_ao + (size_t)(m0 + lr[i])*CDIM + k0 + lk[i]);
                bbuf[i] = *(const float4*)(w + (size_t)(n0 + lr[i])*CDIM + k0 + lk[i]);
            }
        }

        #pragma unroll
        for (int ks = 0; ks < 4; ks++) {
            const int kc = ks*8;
            uint32_t a[4][4];
            #pragma unroll
            for (int mi = 0; mi < 4; mi++) {
                int r = wm*64 + mi*16;
                a[mi][0] = __float_as_uint(As[(r+g  )*SPAD + kc + q    ]);
                a[mi][1] = __float_as_uint(As[(r+g+8)*SPAD + kc + q    ]);
                a[mi][2] = __float_as_uint(As[(r+g  )*SPAD + kc + q + 4]);
                a[mi][3] = __float_as_uint(As[(r+g+8)*SPAD + kc + q + 4]);
            }
            uint32_t b[4][2];
            #pragma unroll
            for (int ni = 0; ni < 4; ni++) {
                int cb = wn*32 + ni*8;
                b[ni][0] = __float_as_uint(Bs[(cb+g)*SPAD + kc + q    ]);
                b[ni][1] = __float_as_uint(Bs[(cb+g)*SPAD + kc + q + 4]);
            }
            #pragma unroll
            for (int mi = 0; mi < 4; mi++)
                #pragma unroll
                for (int ni = 0; ni < 4; ni++)
                    mma_tf32(acc[mi][ni], a[mi][0], a[mi][1], a[mi][2], a[mi][3],
                             b[ni][0], b[ni][1]);
        }
        __syncthreads();
    }

    #pragma unroll
    for (int mi = 0; mi < 4; mi++) {
        #pragma unroll
        for (int half = 0; half < 2; half++) {
            int mrow = wm*64 + mi*16 + g + half*8;
            int dstb = rowdst[mrow];
            #pragma unroll
            for (int ni = 0; ni < 4; ni++) {
                int col = n0 + wn*32 + ni*8 + q*2;
                float2 v;
                v.x = acc[mi][ni][half*2+0] + bias[col];
                v.y = acc[mi][ni][half*2+1] + bias[col+1];
                *(float2*)(out + dstb + col) = v;
            }
        }
    }
}

extern "C" void kernel_launch(void* const* d_in, const int* in_sizes, int n_in,
                              void* d_out, int out_size)
{
    const float* x     = (const float*)d_in[0];
    const float* qkvw  = (const float*)d_in[1];
    const float* qkvb  = (const float*)d_in[2];
    const float* projw = (const float*)d_in[3];
    const float* projb = (const float*)d_in[4];
    const float* relt  = (const float*)d_in[5];
    const int*   reli  = (const int*)d_in[6];
    float* out = (float*)d_out;

    bias_pre2<<<(4*NHEAD*NT*NT + 255)/256, 256>>>(relt, reli);
    qkv_tc<<<dim3(TOK/128, QKV_N/128), 256>>>(x, qkvw, qkvb);
    attn_tc3<<<dim3(BW, NHEAD), 128>>>();
    proj_tc<<<dim3(TOK/128, CDIM/128), 256>>>(projw, projb, out);
}

// round 6
// speedup vs baseline: 1.4388x; 1.4388x over previous
#include <cuda_runtime.h>
#include <math.h>
#include <stdint.h>

#define BATCH 32
#define HDIM 56
#define WDIM 56
#define CDIM 256
#define NHEAD 8
#define HEADD 32
#define WS 7
#define NT 49
#define SHIFT 3
#define NWIN 64
#define BW (BATCH*NWIN)
#define TOK (BW*NT)
#define QKV_N 768
#define SPAD 36
#define SSTR 60

// Static device scratch (allocation-free rule).
__device__ float g_q[BW*NHEAD*NT*HEADD];
__device__ float g_k[BW*NHEAD*NT*HEADD];
__device__ float g_v[BW*NHEAD*NT*HEADD];
__device__ float g_ao[TOK*CDIM];
__device__ float g_bias[4*NHEAD*NT*NT];   // fused (bias + shift-mask) per class/head

__device__ __forceinline__ uint32_t f2tf(float f) {
    uint32_t u;
    asm("cvt.rna.tf32.f32 %0, %1;" : "=r"(u) : "f"(f));
    return u;
}
__device__ __forceinline__ float f2tff(float f) {
    return __uint_as_float(f2tf(f));
}

__device__ __forceinline__ void mma_tf32(float c[4],
                                         uint32_t a0, uint32_t a1, uint32_t a2, uint32_t a3,
                                         uint32_t b0, uint32_t b1) {
    asm volatile(
        "mma.sync.aligned.m16n8k8.row.col.f32.tf32.tf32.f32 "
        "{%0,%1,%2,%3}, {%4,%5,%6,%7}, {%8,%9}, {%0,%1,%2,%3};\n"
        : "+f"(c[0]), "+f"(c[1]), "+f"(c[2]), "+f"(c[3])
        : "r"(a0), "r"(a1), "r"(a2), "r"(a3), "r"(b0), "r"(b1));
}

// ---------------------------------------------------------------------------
// Fused bias + shift-mask precompute. cls bit1 = (wh==7), bit0 = (ww==7).
// ---------------------------------------------------------------------------
__global__ void bias_pre2(const float* __restrict__ relt, const int* __restrict__ reli) {
    int idx = blockIdx.x * 256 + threadIdx.x;
    if (idx >= 4*NHEAD*NT*NT) return;
    int cls = idx / (NHEAD*NT*NT);
    int rem = idx - cls*(NHEAD*NT*NT);
    int nh  = rem / (NT*NT);
    int ij  = rem - nh*(NT*NT);
    int i = ij / NT, j = ij - (ij/NT)*NT;
    float b = relt[reli[ij]*NHEAD + nh];
    int ri = i / WS, ci = i - (i/WS)*WS;
    int rj = j / WS, cj = j - (j/WS)*WS;
    int ghi = (cls & 2) ? ((ri < 4) ? 1 : 2) : 0;
    int gwi = (cls & 1) ? ((ci < 4) ? 1 : 2) : 0;
    int ghj = (cls & 2) ? ((rj < 4) ? 1 : 2) : 0;
    int gwj = (cls & 1) ? ((cj < 4) ? 1 : 2) : 0;
    float mk = (ghi == ghj && gwi == gwj) ? 0.f : -100.f;
    g_bias[idx] = b + mk;
}

// ---------------------------------------------------------------------------
// QKV GEMM (tf32 tensor cores)
// ---------------------------------------------------------------------------
__global__ __launch_bounds__(256) void qkv_tc(
    const float* __restrict__ x,
    const float* __restrict__ w,
    const float* __restrict__ bias)
{
    __shared__ __align__(16) float As[128*SPAD];
    __shared__ __align__(16) float Bs[128*SPAD];
    __shared__ int rowoff[128];

    const int tid = threadIdx.x;
    const int m0 = blockIdx.x * 128;
    const int n0 = blockIdx.y * 128;

    if (tid < 128) {
        int m  = m0 + tid;
        int bw = m / NT; int t = m - bw*NT;
        int b  = bw >> 6; int wi = bw & 63;
        int wh = wi >> 3; int wwn = wi & 7;
        int r  = t / WS;  int c = t - r*WS;
        int hs = wh*WS + r + SHIFT; if (hs >= HDIM) hs -= HDIM;
        int ws = wwn*WS + c + SHIFT; if (ws >= WDIM) ws -= WDIM;
        rowoff[tid] = ((b*HDIM + hs)*WDIM + ws) * CDIM;
    }
    __syncthreads();

    const int warp = tid >> 5, lane = tid & 31;
    const int wm = warp >> 2, wn = warp & 3;
    const int g = lane >> 2, q = lane & 3;

    float acc[4][4][4];
    #pragma unroll
    for (int mi = 0; mi < 4; mi++)
        #pragma unroll
        for (int ni = 0; ni < 4; ni++)
            #pragma unroll
            for (int e = 0; e < 4; e++) acc[mi][ni][e] = 0.f;

    int lr[4], lk[4];
    #pragma unroll
    for (int i = 0; i < 4; i++) {
        int lin = tid + i*256;
        lr[i] = lin >> 3;
        lk[i] = (lin & 7) * 4;
    }

    float4 abuf[4], bbuf[4];
    #pragma unroll
    for (int i = 0; i < 4; i++) {
        abuf[i] = *(const float4*)(x + rowoff[lr[i]] + lk[i]);
        bbuf[i] = *(const float4*)(w + (size_t)(n0 + lr[i])*CDIM + lk[i]);
    }

    for (int kt = 0; kt < 8; kt++) {
        #pragma unroll
        for (int i = 0; i < 4; i++) {
            float* ap = &As[lr[i]*SPAD + lk[i]];
            ap[0] = f2tff(abuf[i].x); ap[1] = f2tff(abuf[i].y);
            ap[2] = f2tff(abuf[i].z); ap[3] = f2tff(abuf[i].w);
            float* bp = &Bs[lr[i]*SPAD + lk[i]];
            bp[0] = f2tff(bbuf[i].x); bp[1] = f2tff(bbuf[i].y);
            bp[2] = f2tff(bbuf[i].z); bp[3] = f2tff(bbuf[i].w);
        }
        __syncthreads();

        if (kt < 7) {
            int k0 = (kt+1)*32;
            #pragma unroll
            for (int i = 0; i < 4; i++) {
                abuf[i] = *(const float4*)(x + rowoff[lr[i]] + k0 + lk[i]);
                bbuf[i] = *(const float4*)(w + (size_t)(n0 + lr[i])*CDIM + k0 + lk[i]);
            }
        }

        #pragma unroll
        for (int ks = 0; ks < 4; ks++) {
            const int kc = ks*8;
            uint32_t a[4][4];
            #pragma unroll
            for (int mi = 0; mi < 4; mi++) {
                int r = wm*64 + mi*16;
                a[mi][0] = __float_as_uint(As[(r+g  )*SPAD + kc + q    ]);
                a[mi][1] = __float_as_uint(As[(r+g+8)*SPAD + kc + q    ]);
                a[mi][2] = __float_as_uint(As[(r+g  )*SPAD + kc + q + 4]);
                a[mi][3] = __float_as_uint(As[(r+g+8)*SPAD + kc + q + 4]);
            }
            uint32_t b[4][2];
            #pragma unroll
            for (int ni = 0; ni < 4; ni++) {
                int cb = wn*32 + ni*8;
                b[ni][0] = __float_as_uint(Bs[(cb+g)*SPAD + kc + q    ]);
                b[ni][1] = __float_as_uint(Bs[(cb+g)*SPAD + kc + q + 4]);
            }
            #pragma unroll
            for (int mi = 0; mi < 4; mi++)
                #pragma unroll
                for (int ni = 0; ni < 4; ni++)
                    mma_tf32(acc[mi][ni], a[mi][0], a[mi][1], a[mi][2], a[mi][3],
                             b[ni][0], b[ni][1]);
        }
        __syncthreads();
    }

    const float scale = 0.17677669529663687f;
    #pragma unroll
    for (int mi = 0; mi < 4; mi++) {
        #pragma unroll
        for (int half = 0; half < 2; half++) {
            int mrow = wm*64 + mi*16 + g + half*8;
            int m  = m0 + mrow;
            int bw = m / NT; int t = m - bw*NT;
            int base = bw*12544 + t*32;
            #pragma unroll
            for (int ni = 0; ni < 4; ni++) {
                int col = n0 + wn*32 + ni*8 + q*2;
                float v0 = acc[mi][ni][half*2+0] + bias[col];
                float v1 = acc[mi][ni][half*2+1] + bias[col+1];
                int which = col >> 8;
                int rem   = col & 255;
                int nh = rem >> 5; int d = rem & 31;
                int dst = base + nh*1568 + d;
                if (which == 0)      { g_q[dst] = v0*scale; g_q[dst+1] = v1*scale; }
                else if (which == 1) { g_k[dst] = v0;       g_k[dst+1] = v1; }
                else                 { g_v[dst] = v0;       g_v[dst+1] = v1; }
            }
        }
    }
}

// ---------------------------------------------------------------------------
// Attention v3: 128 threads/block, one (window, head) per block.
// Warp w owns S-rows [16w, 16w+16): S = QK^T via mma (A cached in regs),
// softmax fully in registers (quad shuffles), P -> smem (aliased over Q),
// O = P V via mma.
// ---------------------------------------------------------------------------
__global__ __launch_bounds__(128) void attn_tc3()
{
    __shared__ __align__(16) float sbuf[NT*SSTR];   // P (49x60); prologue holds Q (49x36)
    __shared__ __align__(16) float sk[NT*SPAD];
    __shared__ __align__(16) float svt[HEADD*SSTR]; // V^T, cols 49..55 zeroed

    const int bw = blockIdx.x;
    const int nh = blockIdx.y;
    const int tid = threadIdx.x;

    const float* qb = g_q + bw*12544 + nh*1568;
    const float* kb = g_k + bw*12544 + nh*1568;
    const float* vb = g_v + bw*12544 + nh*1568;

    for (int i = tid; i < 392; i += 128) {
        int e = i*4; int t = e >> 5; int d = e & 31;
        float4 q4 = *(const float4*)(qb + e);
        float4 k4 = *(const float4*)(kb + e);
        float4 v4 = *(const float4*)(vb + e);
        float* qp = &sbuf[t*SPAD + d];
        qp[0]=f2tff(q4.x); qp[1]=f2tff(q4.y); qp[2]=f2tff(q4.z); qp[3]=f2tff(q4.w);
        float* kp = &sk[t*SPAD + d];
        kp[0]=f2tff(k4.x); kp[1]=f2tff(k4.y); kp[2]=f2tff(k4.z); kp[3]=f2tff(k4.w);
        svt[(d+0)*SSTR + t] = f2tff(v4.x);
        svt[(d+1)*SSTR + t] = f2tff(v4.y);
        svt[(d+2)*SSTR + t] = f2tff(v4.z);
        svt[(d+3)*SSTR + t] = f2tff(v4.w);
    }
    for (int i = tid; i < 224; i += 128)
        svt[(i/7)*SSTR + 49 + (i - (i/7)*7)] = 0.f;
    __syncthreads();

    const int warp = tid >> 5, lane = tid & 31;
    const int g = lane >> 2, q = lane & 3;

    const int wi  = bw & 63;
    const int cls = ((((wi >> 3) == 7) ? 2 : 0) | (((wi & 7) == 7) ? 1 : 0));
    const float* bb = g_bias + (cls*NHEAD + nh)*(NT*NT);

    const int i0 = warp*16;
    const int r0 = i0 + g, r1 = r0 + 8;
    const int ra = min(r0, 48), rb = min(r1, 48);
    const bool v0ok = (r0 < 49), v1ok = (r1 < 49);

    // ---- S = Q K^T (A fragments cached across all 7 n-tiles) ----
    uint32_t a[4][4];
    #pragma unroll
    for (int k4i = 0; k4i < 4; k4i++) {
        int kc = k4i*8;
        a[k4i][0] = __float_as_uint(sbuf[ra*SPAD + kc + q    ]);
        a[k4i][1] = __float_as_uint(sbuf[rb*SPAD + kc + q    ]);
        a[k4i][2] = __float_as_uint(sbuf[ra*SPAD + kc + q + 4]);
        a[k4i][3] = __float_as_uint(sbuf[rb*SPAD + kc + q + 4]);
    }
    float c[7][4];
    #pragma unroll
    for (int nt = 0; nt < 7; nt++) { c[nt][0]=0.f; c[nt][1]=0.f; c[nt][2]=0.f; c[nt][3]=0.f; }
    #pragma unroll
    for (int nt = 0; nt < 7; nt++) {
        int rn = min(nt*8 + g, 48);
        #pragma unroll
        for (int k4i = 0; k4i < 4; k4i++) {
            int kc = k4i*8;
            uint32_t b0 = __float_as_uint(sk[rn*SPAD + kc + q    ]);
            uint32_t b1 = __float_as_uint(sk[rn*SPAD + kc + q + 4]);
            mma_tf32(c[nt], a[k4i][0], a[k4i][1], a[k4i][2], a[k4i][3], b0, b1);
        }
    }

    // ---- bias(+mask) add, in-register ----
    float mx0 = -1e30f, mx1 = -1e30f;
    #pragma unroll
    for (int nt = 0; nt < 7; nt++) {
        #pragma unroll
        for (int bc = 0; bc < 2; bc++) {
            int col = nt*8 + 2*q + bc;
            bool cok = (col < 49);
            float t0 = (v0ok && cok) ? (c[nt][bc]   + __ldg(&bb[r0*NT + col])) : -1e30f;
            float t1 = (v1ok && cok) ? (c[nt][2+bc] + __ldg(&bb[r1*NT + col])) : -1e30f;
            c[nt][bc]   = t0;
            c[nt][2+bc] = t1;
            mx0 = fmaxf(mx0, t0);
            mx1 = fmaxf(mx1, t1);
        }
    }
    __syncthreads();   // all reads of sbuf(Q)/sk done; sbuf can be reused as P

    // ---- softmax in registers (rows live in lane quads) ----
    mx0 = fmaxf(mx0, __shfl_xor_sync(0xffffffffu, mx0, 1));
    mx0 = fmaxf(mx0, __shfl_xor_sync(0xffffffffu, mx0, 2));
    mx1 = fmaxf(mx1, __shfl_xor_sync(0xffffffffu, mx1, 1));
    mx1 = fmaxf(mx1, __shfl_xor_sync(0xffffffffu, mx1, 2));
    float s0 = 0.f, s1 = 0.f;
    #pragma unroll
    for (int nt = 0; nt < 7; nt++) {
        c[nt][0] = __expf(c[nt][0] - mx0); s0 += c[nt][0];
        c[nt][1] = __expf(c[nt][1] - mx0); s0 += c[nt][1];
        c[nt][2] = __expf(c[nt][2] - mx1); s1 += c[nt][2];
        c[nt][3] = __expf(c[nt][3] - mx1); s1 += c[nt][3];
    }
    s0 += __shfl_xor_sync(0xffffffffu, s0, 1);
    s0 += __shfl_xor_sync(0xffffffffu, s0, 2);
    s1 += __shfl_xor_sync(0xffffffffu, s1, 1);
    s1 += __shfl_xor_sync(0xffffffffu, s1, 2);
    float inv0 = 1.f / s0, inv1 = 1.f / s1;
    #pragma unroll
    for (int nt = 0; nt < 7; nt++) {
        #pragma unroll
        for (int bc = 0; bc < 2; bc++) {
            int col = nt*8 + 2*q + bc;
            if (v0ok) sbuf[r0*SSTR + col] = (col < 49) ? f2tff(c[nt][bc]  *inv0) : 0.f;
            if (v1ok) sbuf[r1*SSTR + col] = (col < 49) ? f2tff(c[nt][2+bc]*inv1) : 0.f;
        }
    }
    __syncthreads();

    // ---- O = P V (warp keeps its rows; P fragments hoisted across d-tiles) ----
    uint32_t pa[7][4];
    #pragma unroll
    for (int k7 = 0; k7 < 7; k7++) {
        int kc = k7*8;
        pa[k7][0] = __float_as_uint(sbuf[ra*SSTR + kc + q    ]);
        pa[k7][1] = __float_as_uint(sbuf[rb*SSTR + kc + q    ]);
        pa[k7][2] = __float_as_uint(sbuf[ra*SSTR + kc + q + 4]);
        pa[k7][3] = __float_as_uint(sbuf[rb*SSTR + kc + q + 4]);
    }
    #pragma unroll
    for (int nt = 0; nt < 4; nt++) {
        int n0 = nt*8;
        float cc[4] = {0.f, 0.f, 0.f, 0.f};
        #pragma unroll
        for (int k7 = 0; k7 < 7; k7++) {
            int kc = k7*8;
            uint32_t b0 = __float_as_uint(svt[(n0+g)*SSTR + kc + q    ]);
            uint32_t b1 = __float_as_uint(svt[(n0+g)*SSTR + kc + q + 4]);
            mma_tf32(cc, pa[k7][0], pa[k7][1], pa[k7][2], pa[k7][3], b0, b1);
        }
        int col = nh*32 + n0 + 2*q;
        if (v0ok)
            *(float2*)(g_ao + (size_t)(bw*NT + r0)*CDIM + col) = make_float2(cc[0], cc[1]);
        if (v1ok)
            *(float2*)(g_ao + (size_t)(bw*NT + r1)*CDIM + col) = make_float2(cc[2], cc[3]);
    }
}

// ---------------------------------------------------------------------------
// Proj GEMM (tf32 tensor cores) with fused window-reverse + un-shift scatter.
// ---------------------------------------------------------------------------
__global__ __launch_bounds__(256) void proj_tc(
    const float* __restrict__ w,
    const float* __restrict__ bias,
    float* __restrict__ out)
{
    __shared__ __align__(16) float As[128*SPAD];
    __shared__ __align__(16) float Bs[128*SPAD];
    __shared__ int rowdst[128];

    const int tid = threadIdx.x;
    const int m0 = blockIdx.x * 128;
    const int n0 = blockIdx.y * 128;

    if (tid < 128) {
        int m  = m0 + tid;
        int bw = m / NT; int t = m - bw*NT;
        int b  = bw >> 6; int wi = bw & 63;
        int wh = wi >> 3; int wwn = wi & 7;
        int r  = t / WS;  int c = t - r*WS;
        int hd = wh*WS + r + SHIFT; if (hd >= HDIM) hd -= HDIM;
        int wd = wwn*WS + c + SHIFT; if (wd >= WDIM) wd -= WDIM;
        rowdst[tid] = ((b*HDIM + hd)*WDIM + wd) * CDIM;
    }
    __syncthreads();

    const int warp = tid >> 5, lane = tid & 31;
    const int wm = warp >> 2, wn = warp & 3;
    const int g = lane >> 2, q = lane & 3;

    float acc[4][4][4];
    #pragma unroll
    for (int mi = 0; mi < 4; mi++)
        #pragma unroll
        for (int ni = 0; ni < 4; ni++)
            #pragma unroll
            for (int e = 0; e < 4; e++) acc[mi][ni][e] = 0.f;

    int lr[4], lk[4];
    #pragma unroll
    for (int i = 0; i < 4; i++) {
        int lin = tid + i*256;
        lr[i] = lin >> 3;
        lk[i] = (lin & 7) * 4;
    }

    float4 abuf[4], bbuf[4];
    #pragma unroll
    for (int i = 0; i < 4; i++) {
        abuf[i] = *(const float4*)(g_ao + (size_t)(m0 + lr[i])*CDIM + lk[i]);
        bbuf[i] = *(const float4*)(w + (size_t)(n0 + lr[i])*CDIM + lk[i]);
    }

    for (int kt = 0; kt < 8; kt++) {
        #pragma unroll
        for (int i = 0; i < 4; i++) {
            float* ap = &As[lr[i]*SPAD + lk[i]];
            ap[0] = f2tff(abuf[i].x); ap[1] = f2tff(abuf[i].y);
            ap[2] = f2tff(abuf[i].z); ap[3] = f2tff(abuf[i].w);
            float* bp = &Bs[lr[i]*SPAD + lk[i]];
            bp[0] = f2tff(bbuf[i].x); bp[1] = f2tff(bbuf[i].y);
            bp[2] = f2tff(bbuf[i].z); bp[3] = f2tff(bbuf[i].w);
        }
        __syncthreads();

        if (kt < 7) {
            int k0 = (kt+1)*32;
            #pragma unroll
            for (int i = 0; i < 4; i++) {
                abuf[i] = *(const float4*)(g_ao + (size_t)(m0 + lr[i])*CDIM + k0 + lk[i]);
                bbuf[i] = *(const float4*)(w + (size_t)(n0 + lr[i])*CDIM + k0 + lk[i]);
            }
        }

        #pragma unroll
        for (int ks = 0; ks < 4; ks++) {
            const int kc = ks*8;
            uint32_t a[4][4];
            #pragma unroll
            for (int mi = 0; mi < 4; mi++) {
                int r = wm*64 + mi*16;
                a[mi][0] = __float_as_uint(As[(r+g  )*SPAD + kc + q    ]);
                a[mi][1] = __float_as_uint(As[(r+g+8)*SPAD + kc + q    ]);
                a[mi][2] = __float_as_uint(As[(r+g  )*SPAD + kc + q + 4]);
                a[mi][3] = __float_as_uint(As[(r+g+8)*SPAD + kc + q + 4]);
            }
            uint32_t b[4][2];
            #pragma unroll
            for (int ni = 0; ni < 4; ni++) {
                int cb = wn*32 + ni*8;
                b[ni][0] = __float_as_uint(Bs[(cb+g)*SPAD + kc + q    ]);
                b[ni][1] = __float_as_uint(Bs[(cb+g)*SPAD + kc + q + 4]);
            }
            #pragma unroll
            for (int mi = 0; mi < 4; mi++)
                #pragma unroll
                for (int ni = 0; ni < 4; ni++)
                    mma_tf32(acc[mi][ni], a[mi][0], a[mi][1], a[mi][2], a[mi][3],
                             b[ni][0], b[ni][1]);
        }
        __syncthreads();
    }

    #pragma unroll
    for (int mi = 0; mi < 4; mi++) {
        #pragma unroll
        for (int half = 0; half < 2; half++) {
            int mrow = wm*64 + mi*16 + g + half*8;
            int dstb = rowdst[mrow];
            #pragma unroll
            for (int ni = 0; ni < 4; ni++) {
                int col = n0 + wn*32 + ni*8 + q*2;
                float2 v;
                v.x = acc[mi][ni][half*2+0] + bias[col];
                v.y = acc[mi][ni][half*2+1] + bias[col+1];
                *(float2*)(out + dstb + col) = v;
            }
        }
    }
}

extern "C" void kernel_launch(void* const* d_in, const int* in_sizes, int n_in,
                              void* d_out, int out_size)
{
    const float* x     = (const float*)d_in[0];
    const float* qkvw  = (const float*)d_in[1];
    const float* qkvb  = (const float*)d_in[2];
    const float* projw = (const float*)d_in[3];
    const float* projb = (const float*)d_in[4];
    const float* relt  = (const float*)d_in[5];
    const int*   reli  = (const int*)d_in[6];
    float* out = (float*)d_out;

    bias_pre2<<<(4*NHEAD*NT*NT + 255)/256, 256>>>(relt, reli);
    qkv_tc<<<dim3(TOK/128, QKV_N/128), 256>>>(x, qkvw, qkvb);
    attn_tc3<<<dim3(BW, NHEAD), 128>>>();
    proj_tc<<<dim3(TOK/128, CDIM/128), 256>>>(projw, projb, out);
}

// round 7
// speedup vs baseline: 1.7342x; 1.2053x over previous
#include <cuda_runtime.h>
#include <math.h>
#include <stdint.h>

#define BATCH 32
#define HDIM 56
#define WDIM 56
#define CDIM 256
#define NHEAD 8
#define HEADD 32
#define WS 7
#define NT 49
#define SHIFT 3
#define NWIN 64
#define BW (BATCH*NWIN)
#define TOK (BW*NT)
#define QKV_N 768
#define SPAD 36
#define SSTR 60

// Static device scratch (allocation-free rule).
__device__ float g_q[BW*NHEAD*NT*HEADD];
__device__ float g_k[BW*NHEAD*NT*HEADD];
__device__ float g_v[BW*NHEAD*NT*HEADD];
__device__ float g_ao[TOK*CDIM];
__device__ float g_bias[4*NHEAD*NT*NT];   // fused (bias + shift-mask) per class/head

__device__ __forceinline__ uint32_t f2tf(float f) {
    uint32_t u;
    asm("cvt.rna.tf32.f32 %0, %1;" : "=r"(u) : "f"(f));
    return u;
}
__device__ __forceinline__ float f2tff(float f) {
    return __uint_as_float(f2tf(f));
}

__device__ __forceinline__ uint32_t smem_u32(const void* p) {
    return (uint32_t)__cvta_generic_to_shared(p);
}

__device__ __forceinline__ void ldsm_x4(uint32_t& r0, uint32_t& r1, uint32_t& r2, uint32_t& r3,
                                        uint32_t addr) {
    asm volatile("ldmatrix.sync.aligned.m8n8.x4.shared.b16 {%0,%1,%2,%3}, [%4];"
                 : "=r"(r0), "=r"(r1), "=r"(r2), "=r"(r3) : "r"(addr));
}
__device__ __forceinline__ void ldsm_x2(uint32_t& r0, uint32_t& r1, uint32_t addr) {
    asm volatile("ldmatrix.sync.aligned.m8n8.x2.shared.b16 {%0,%1}, [%2];"
                 : "=r"(r0), "=r"(r1) : "r"(addr));
}

__device__ __forceinline__ void mma_tf32(float c[4],
                                         uint32_t a0, uint32_t a1, uint32_t a2, uint32_t a3,
                                         uint32_t b0, uint32_t b1) {
    asm volatile(
        "mma.sync.aligned.m16n8k8.row.col.f32.tf32.tf32.f32 "
        "{%0,%1,%2,%3}, {%4,%5,%6,%7}, {%8,%9}, {%0,%1,%2,%3};\n"
        : "+f"(c[0]), "+f"(c[1]), "+f"(c[2]), "+f"(c[3])
        : "r"(a0), "r"(a1), "r"(a2), "r"(a3), "r"(b0), "r"(b1));
}

// ---------------------------------------------------------------------------
// Fused bias + shift-mask precompute. cls bit1 = (wh==7), bit0 = (ww==7).
// ---------------------------------------------------------------------------
__global__ void bias_pre2(const float* __restrict__ relt, const int* __restrict__ reli) {
    int idx = blockIdx.x * 256 + threadIdx.x;
    if (idx >= 4*NHEAD*NT*NT) return;
    int cls = idx / (NHEAD*NT*NT);
    int rem = idx - cls*(NHEAD*NT*NT);
    int nh  = rem / (NT*NT);
    int ij  = rem - nh*(NT*NT);
    int i = ij / NT, j = ij - (ij/NT)*NT;
    float b = relt[reli[ij]*NHEAD + nh];
    int ri = i / WS, ci = i - (i/WS)*WS;
    int rj = j / WS, cj = j - (j/WS)*WS;
    int ghi = (cls & 2) ? ((ri < 4) ? 1 : 2) : 0;
    int gwi = (cls & 1) ? ((ci < 4) ? 1 : 2) : 0;
    int ghj = (cls & 2) ? ((rj < 4) ? 1 : 2) : 0;
    int gwj = (cls & 1) ? ((cj < 4) ? 1 : 2) : 0;
    float mk = (ghi == ghj && gwi == gwj) ? 0.f : -100.f;
    g_bias[idx] = b + mk;
}

// ---------------------------------------------------------------------------
// QKV GEMM (tf32 tensor cores + ldmatrix fragment loads)
// ---------------------------------------------------------------------------
__global__ __launch_bounds__(256) void qkv_tc(
    const float* __restrict__ x,
    const float* __restrict__ w,
    const float* __restrict__ bias)
{
    __shared__ __align__(16) float As[128*SPAD];
    __shared__ __align__(16) float Bs[128*SPAD];
    __shared__ int rowoff[128];

    const int tid = threadIdx.x;
    const int m0 = blockIdx.x * 128;
    const int n0 = blockIdx.y * 128;

    if (tid < 128) {
        int m  = m0 + tid;
        int bw = m / NT; int t = m - bw*NT;
        int b  = bw >> 6; int wi = bw & 63;
        int wh = wi >> 3; int wwn = wi & 7;
        int r  = t / WS;  int c = t - r*WS;
        int hs = wh*WS + r + SHIFT; if (hs >= HDIM) hs -= HDIM;
        int ws = wwn*WS + c + SHIFT; if (ws >= WDIM) ws -= WDIM;
        rowoff[tid] = ((b*HDIM + hs)*WDIM + ws) * CDIM;
    }
    __syncthreads();

    const int warp = tid >> 5, lane = tid & 31;
    const int wm = warp >> 2, wn = warp & 3;
    const int g = lane >> 2, q = lane & 3;
    const int lt = lane >> 3, lr8 = lane & 7;

    float acc[4][4][4];
    #pragma unroll
    for (int mi = 0; mi < 4; mi++)
        #pragma unroll
        for (int ni = 0; ni < 4; ni++)
            #pragma unroll
            for (int e = 0; e < 4; e++) acc[mi][ni][e] = 0.f;

    // per-lane ldmatrix base addresses (constant across k-tiles)
    uint32_t a_addr[4], b_addr[4];
    #pragma unroll
    for (int mi = 0; mi < 4; mi++)
        a_addr[mi] = smem_u32(&As[(wm*64 + mi*16 + (lt&1)*8 + lr8)*SPAD + (lt>>1)*4]);
    #pragma unroll
    for (int ni = 0; ni < 4; ni++)
        b_addr[ni] = smem_u32(&Bs[(wn*32 + ni*8 + lr8)*SPAD + (lt&1)*4]);

    int lr[4], lk[4];
    #pragma unroll
    for (int i = 0; i < 4; i++) {
        int lin = tid + i*256;
        lr[i] = lin >> 3;
        lk[i] = (lin & 7) * 4;
    }

    float4 abuf[4], bbuf[4];
    #pragma unroll
    for (int i = 0; i < 4; i++) {
        abuf[i] = *(const float4*)(x + rowoff[lr[i]] + lk[i]);
        bbuf[i] = *(const float4*)(w + (size_t)(n0 + lr[i])*CDIM + lk[i]);
    }

    for (int kt = 0; kt < 8; kt++) {
        #pragma unroll
        for (int i = 0; i < 4; i++) {
            float* ap = &As[lr[i]*SPAD + lk[i]];
            ap[0] = f2tff(abuf[i].x); ap[1] = f2tff(abuf[i].y);
            ap[2] = f2tff(abuf[i].z); ap[3] = f2tff(abuf[i].w);
            float* bp = &Bs[lr[i]*SPAD + lk[i]];
            bp[0] = f2tff(bbuf[i].x); bp[1] = f2tff(bbuf[i].y);
            bp[2] = f2tff(bbuf[i].z); bp[3] = f2tff(bbuf[i].w);
        }
        __syncthreads();

        if (kt < 7) {
            int k0 = (kt+1)*32;
            #pragma unroll
            for (int i = 0; i < 4; i++) {
                abuf[i] = *(const float4*)(x + rowoff[lr[i]] + k0 + lk[i]);
                bbuf[i] = *(const float4*)(w + (size_t)(n0 + lr[i])*CDIM + k0 + lk[i]);
            }
        }

        #pragma unroll
        for (int ks = 0; ks < 4; ks++) {
            const uint32_t ko = ks*32;   // ks*8 floats
            uint32_t a[4][4];
            #pragma unroll
            for (int mi = 0; mi < 4; mi++)
                ldsm_x4(a[mi][0], a[mi][1], a[mi][2], a[mi][3], a_addr[mi] + ko);
            uint32_t b[4][2];
            #pragma unroll
            for (int ni = 0; ni < 4; ni++)
                ldsm_x2(b[ni][0], b[ni][1], b_addr[ni] + ko);
            #pragma unroll
            for (int mi = 0; mi < 4; mi++)
                #pragma unroll
                for (int ni = 0; ni < 4; ni++)
                    mma_tf32(acc[mi][ni], a[mi][0], a[mi][1], a[mi][2], a[mi][3],
                             b[ni][0], b[ni][1]);
        }
        __syncthreads();
    }

    const float scale = 0.17677669529663687f;
    #pragma unroll
    for (int mi = 0; mi < 4; mi++) {
        #pragma unroll
        for (int half = 0; half < 2; half++) {
            int mrow = wm*64 + mi*16 + g + half*8;
            int m  = m0 + mrow;
            int bw = m / NT; int t = m - bw*NT;
            int base = bw*12544 + t*32;
            #pragma unroll
            for (int ni = 0; ni < 4; ni++) {
                int col = n0 + wn*32 + ni*8 + q*2;
                float v0 = acc[mi][ni][half*2+0] + bias[col];
                float v1 = acc[mi][ni][half*2+1] + bias[col+1];
                int which = col >> 8;
                int rem   = col & 255;
                int nh = rem >> 5; int d = rem & 31;
                int dst = base + nh*1568 + d;
                if (which == 0)      { g_q[dst] = v0*scale; g_q[dst+1] = v1*scale; }
                else if (which == 1) { g_k[dst] = v0;       g_k[dst+1] = v1; }
                else                 { g_v[dst] = v0;       g_v[dst+1] = v1; }
            }
        }
    }
}

// ---------------------------------------------------------------------------
// Attention v4: 128 threads/block, one (window, head) per block, ldmatrix
// fragment loads everywhere. Warp w owns S-rows [16w, 16w+16).
// ---------------------------------------------------------------------------
__global__ __launch_bounds__(128) void attn_tc4()
{
    __shared__ __align__(16) float sbuf[NT*SSTR];   // P (49x60); prologue holds Q (49x36)
    __shared__ __align__(16) float sk[NT*SPAD];
    __shared__ __align__(16) float svt[HEADD*SSTR]; // V^T, cols 49..55 zeroed

    const int bw = blockIdx.x;
    const int nh = blockIdx.y;
    const int tid = threadIdx.x;

    const float* qb = g_q + bw*12544 + nh*1568;
    const float* kb = g_k + bw*12544 + nh*1568;
    const float* vb = g_v + bw*12544 + nh*1568;

    for (int i = tid; i < 392; i += 128) {
        int e = i*4; int t = e >> 5; int d = e & 31;
        float4 q4 = *(const float4*)(qb + e);
        float4 k4 = *(const float4*)(kb + e);
        float4 v4 = *(const float4*)(vb + e);
        float* qp = &sbuf[t*SPAD + d];
        qp[0]=f2tff(q4.x); qp[1]=f2tff(q4.y); qp[2]=f2tff(q4.z); qp[3]=f2tff(q4.w);
        float* kp = &sk[t*SPAD + d];
        kp[0]=f2tff(k4.x); kp[1]=f2tff(k4.y); kp[2]=f2tff(k4.z); kp[3]=f2tff(k4.w);
        svt[(d+0)*SSTR + t] = f2tff(v4.x);
        svt[(d+1)*SSTR + t] = f2tff(v4.y);
        svt[(d+2)*SSTR + t] = f2tff(v4.z);
        svt[(d+3)*SSTR + t] = f2tff(v4.w);
    }
    for (int i = tid; i < 224; i += 128)
        svt[(i/7)*SSTR + 49 + (i - (i/7)*7)] = 0.f;
    __syncthreads();

    const int warp = tid >> 5, lane = tid & 31;
    const int g = lane >> 2, q = lane & 3;
    const int lt = lane >> 3, lr8 = lane & 7;

    const int wi  = bw & 63;
    const int cls = ((((wi >> 3) == 7) ? 2 : 0) | (((wi & 7) == 7) ? 1 : 0));
    const float* bb = g_bias + (cls*NHEAD + nh)*(NT*NT);

    const int i0 = warp*16;
    const int r0 = i0 + g, r1 = r0 + 8;
    const bool v0ok = (r0 < 49), v1ok = (r1 < 49);

    // ---- S = Q K^T via ldmatrix + mma ----
    const int arow = min(i0 + (lt&1)*8 + lr8, 48);
    uint32_t qaddr = smem_u32(&sbuf[arow*SPAD + (lt>>1)*4]);
    uint32_t a[4][4];
    #pragma unroll
    for (int k4i = 0; k4i < 4; k4i++)
        ldsm_x4(a[k4i][0], a[k4i][1], a[k4i][2], a[k4i][3], qaddr + k4i*32);

    float c[7][4];
    #pragma unroll
    for (int nt = 0; nt < 7; nt++) { c[nt][0]=0.f; c[nt][1]=0.f; c[nt][2]=0.f; c[nt][3]=0.f; }
    #pragma unroll
    for (int nt = 0; nt < 7; nt++) {
        uint32_t kaddr = smem_u32(&sk[min(nt*8 + lr8, 48)*SPAD + (lt&1)*4]);
        #pragma unroll
        for (int k4i = 0; k4i < 4; k4i++) {
            uint32_t b0, b1;
            ldsm_x2(b0, b1, kaddr + k4i*32);
            mma_tf32(c[nt], a[k4i][0], a[k4i][1], a[k4i][2], a[k4i][3], b0, b1);
        }
    }

    // ---- bias(+mask) add, in-register ----
    float mx0 = -1e30f, mx1 = -1e30f;
    #pragma unroll
    for (int nt = 0; nt < 7; nt++) {
        #pragma unroll
        for (int bc = 0; bc < 2; bc++) {
            int col = nt*8 + 2*q + bc;
            bool cok = (col < 49);
            float t0 = (v0ok && cok) ? (c[nt][bc]   + __ldg(&bb[r0*NT + col])) : -1e30f;
            float t1 = (v1ok && cok) ? (c[nt][2+bc] + __ldg(&bb[r1*NT + col])) : -1e30f;
            c[nt][bc]   = t0;
            c[nt][2+bc] = t1;
            mx0 = fmaxf(mx0, t0);
            mx1 = fmaxf(mx1, t1);
        }
    }
    __syncthreads();   // done reading sbuf(Q)/sk; sbuf reused as P

    // ---- softmax in registers ----
    mx0 = fmaxf(mx0, __shfl_xor_sync(0xffffffffu, mx0, 1));
    mx0 = fmaxf(mx0, __shfl_xor_sync(0xffffffffu, mx0, 2));
    mx1 = fmaxf(mx1, __shfl_xor_sync(0xffffffffu, mx1, 1));
    mx1 = fmaxf(mx1, __shfl_xor_sync(0xffffffffu, mx1, 2));
    float s0 = 0.f, s1 = 0.f;
    #pragma unroll
    for (int nt = 0; nt < 7; nt++) {
        c[nt][0] = __expf(c[nt][0] - mx0); s0 += c[nt][0];
        c[nt][1] = __expf(c[nt][1] - mx0); s0 += c[nt][1];
        c[nt][2] = __expf(c[nt][2] - mx1); s1 += c[nt][2];
        c[nt][3] = __expf(c[nt][3] - mx1); s1 += c[nt][3];
    }
    s0 += __shfl_xor_sync(0xffffffffu, s0, 1);
    s0 += __shfl_xor_sync(0xffffffffu, s0, 2);
    s1 += __shfl_xor_sync(0xffffffffu, s1, 1);
    s1 += __shfl_xor_sync(0xffffffffu, s1, 2);
    float inv0 = 1.f / s0, inv1 = 1.f / s1;
    #pragma unroll
    for (int nt = 0; nt < 7; nt++) {
        #pragma unroll
        for (int bc = 0; bc < 2; bc++) {
            int col = nt*8 + 2*q + bc;
            if (v0ok) sbuf[r0*SSTR + col] = (col < 49) ? f2tff(c[nt][bc]  *inv0) : 0.f;
            if (v1ok) sbuf[r1*SSTR + col] = (col < 49) ? f2tff(c[nt][2+bc]*inv1) : 0.f;
        }
    }
    __syncthreads();

    // ---- O = P V via ldmatrix + mma ----
    uint32_t paddr = smem_u32(&sbuf[min(i0 + (lt&1)*8 + lr8, 48)*SSTR + (lt>>1)*4]);
    uint32_t pa[7][4];
    #pragma unroll
    for (int k7 = 0; k7 < 7; k7++)
        ldsm_x4(pa[k7][0], pa[k7][1], pa[k7][2], pa[k7][3], paddr + k7*32);

    #pragma unroll
    for (int nt = 0; nt < 4; nt++) {
        int n0 = nt*8;
        uint32_t vaddr = smem_u32(&svt[(n0 + lr8)*SSTR + (lt&1)*4]);
        float cc[4] = {0.f, 0.f, 0.f, 0.f};
        #pragma unroll
        for (int k7 = 0; k7 < 7; k7++) {
            uint32_t b0, b1;
            ldsm_x2(b0, b1, vaddr + k7*32);
            mma_tf32(cc, pa[k7][0], pa[k7][1], pa[k7][2], pa[k7][3], b0, b1);
        }
        int col = nh*32 + n0 + 2*q;
        if (v0ok)
            *(float2*)(g_ao + (size_t)(bw*NT + r0)*CDIM + col) = make_float2(cc[0], cc[1]);
        if (v1ok)
            *(float2*)(g_ao + (size_t)(bw*NT + r1)*CDIM + col) = make_float2(cc[2], cc[3]);
    }
}

// ---------------------------------------------------------------------------
// Proj GEMM (tf32 tensor cores + ldmatrix) with fused reverse-shift scatter.
// ---------------------------------------------------------------------------
__global__ __launch_bounds__(256) void proj_tc(
    const float* __restrict__ w,
    const float* __restrict__ bias,
    float* __restrict__ out)
{
    __shared__ __align__(16) float As[128*SPAD];
    __shared__ __align__(16) float Bs[128*SPAD];
    __shared__ int rowdst[128];

    const int tid = threadIdx.x;
    const int m0 = blockIdx.x * 128;
    const int n0 = blockIdx.y * 128;

    if (tid < 128) {
        int m  = m0 + tid;
        int bw = m / NT; int t = m - bw*NT;
        int b  = bw >> 6; int wi = bw & 63;
        int wh = wi >> 3; int wwn = wi & 7;
        int r  = t / WS;  int c = t - r*WS;
        int hd = wh*WS + r + SHIFT; if (hd >= HDIM) hd -= HDIM;
        int wd = wwn*WS + c + SHIFT; if (wd >= WDIM) wd -= WDIM;
        rowdst[tid] = ((b*HDIM + hd)*WDIM + wd) * CDIM;
    }
    __syncthreads();

    const int warp = tid >> 5, lane = tid & 31;
    const int wm = warp >> 2, wn = warp & 3;
    const int g = lane >> 2, q = lane & 3;
    const int lt = lane >> 3, lr8 = lane & 7;

    float acc[4][4][4];
    #pragma unroll
    for (int mi = 0; mi < 4; mi++)
        #pragma unroll
        for (int ni = 0; ni < 4; ni++)
            #pragma unroll
            for (int e = 0; e < 4; e++) acc[mi][ni][e] = 0.f;

    uint32_t a_addr[4], b_addr[4];
    #pragma unroll
    for (int mi = 0; mi < 4; mi++)
        a_addr[mi] = smem_u32(&As[(wm*64 + mi*16 + (lt&1)*8 + lr8)*SPAD + (lt>>1)*4]);
    #pragma unroll
    for (int ni = 0; ni < 4; ni++)
        b_addr[ni] = smem_u32(&Bs[(wn*32 + ni*8 + lr8)*SPAD + (lt&1)*4]);

    int lr[4], lk[4];
    #pragma unroll
    for (int i = 0; i < 4; i++) {
        int lin = tid + i*256;
        lr[i] = lin >> 3;
        lk[i] = (lin & 7) * 4;
    }

    float4 abuf[4], bbuf[4];
    #pragma unroll
    for (int i = 0; i < 4; i++) {
        abuf[i] = *(const float4*)(g_ao + (size_t)(m0 + lr[i])*CDIM + lk[i]);
        bbuf[i] = *(const float4*)(w + (size_t)(n0 + lr[i])*CDIM + lk[i]);
    }

    for (int kt = 0; kt < 8; kt++) {
        #pragma unroll
        for (int i = 0; i < 4; i++) {
            float* ap = &As[lr[i]*SPAD + lk[i]];
            ap[0] = f2tff(abuf[i].x); ap[1] = f2tff(abuf[i].y);
            ap[2] = f2tff(abuf[i].z); ap[3] = f2tff(abuf[i].w);
            float* bp = &Bs[lr[i]*SPAD + lk[i]];
            bp[0] = f2tff(bbuf[i].x); bp[1] = f2tff(bbuf[i].y);
            bp[2] = f2tff(bbuf[i].z); bp[3] = f2tff(bbuf[i].w);
        }
        __syncthreads();

        if (kt < 7) {
            int k0 = (kt+1)*32;
            #pragma unroll
            for (int i = 0; i < 4; i++) {
                abuf[i] = *(const float4*)(g_ao + (size_t)(m0 + lr[i])*CDIM + k0 + lk[i]);
                bbuf[i] = *(const float4*)(w + (size_t)(n0 + lr[i])*CDIM + k0 + lk[i]);
            }
        }

        #pragma unroll
        for (int ks = 0; ks < 4; ks++) {
            const uint32_t ko = ks*32;
            uint32_t a[4][4];
            #pragma unroll
            for (int mi = 0; mi < 4; mi++)
                ldsm_x4(a[mi][0], a[mi][1], a[mi][2], a[mi][3], a_addr[mi] + ko);
            uint32_t b[4][2];
            #pragma unroll
            for (int ni = 0; ni < 4; ni++)
                ldsm_x2(b[ni][0], b[ni][1], b_addr[ni] + ko);
            #pragma unroll
            for (int mi = 0; mi < 4; mi++)
                #pragma unroll
                for (int ni = 0; ni < 4; ni++)
                    mma_tf32(acc[mi][ni], a[mi][0], a[mi][1], a[mi][2], a[mi][3],
                             b[ni][0], b[ni][1]);
        }
        __syncthreads();
    }

    #pragma unroll
    for (int mi = 0; mi < 4; mi++) {
        #pragma unroll
        for (int half = 0; half < 2; half++) {
            int mrow = wm*64 + mi*16 + g + half*8;
            int dstb = rowdst[mrow];
            #pragma unroll
            for (int ni = 0; ni < 4; ni++) {
                int col = n0 + wn*32 + ni*8 + q*2;
                float2 v;
                v.x = acc[mi][ni][half*2+0] + bias[col];
                v.y = acc[mi][ni][half*2+1] + bias[col+1];
                *(float2*)(out + dstb + col) = v;
            }
        }
    }
}

extern "C" void kernel_launch(void* const* d_in, const int* in_sizes, int n_in,
                              void* d_out, int out_size)
{
    const float* x     = (const float*)d_in[0];
    const float* qkvw  = (const float*)d_in[1];
    const float* qkvb  = (const float*)d_in[2];
    const float* projw = (const float*)d_in[3];
    const float* projb = (const float*)d_in[4];
    const float* relt  = (const float*)d_in[5];
    const int*   reli  = (const int*)d_in[6];
    float* out = (float*)d_out;

    bias_pre2<<<(4*NHEAD*NT*NT + 255)/256, 256>>>(relt, reli);
    qkv_tc<<<dim3(TOK/128, QKV_N/128), 256>>>(x, qkvw, qkvb);
    attn_tc4<<<dim3(BW, NHEAD), 128>>>();
    proj_tc<<<dim3(TOK/128, CDIM/128), 256>>>(projw, projb, out);
}